// round 5
// baseline (speedup 1.0000x reference)
#include <cuda_runtime.h>

#define NCC 68
#define SCALEF 0.125f

typedef unsigned long long u64;
__device__ __forceinline__ u64 pk2(float a, float b){ u64 r; asm("mov.b64 %0,{%1,%2};" : "=l"(r) : "f"(a),"f"(b)); return r; }
__device__ __forceinline__ u64 dup2(float a){ return pk2(a,a); }
__device__ __forceinline__ u64 fma2(u64 a,u64 b,u64 c){ u64 d; asm("fma.rn.f32x2 %0,%1,%2,%3;" : "=l"(d) : "l"(a),"l"(b),"l"(c)); return d; }
__device__ __forceinline__ u64 add2(u64 a,u64 b){ u64 d; asm("add.rn.f32x2 %0,%1,%2;" : "=l"(d) : "l"(a),"l"(b)); return d; }
__device__ __forceinline__ float2 upk(u64 a){ float2 f; asm("mov.b64 {%0,%1},%2;" : "=f"(f.x),"=f"(f.y) : "l"(a)); return f; }

// ---------------- device scratch ----------------
__device__ float g_cbe[NCC*128];
__device__ float g_qg[12*128];
__device__ float g_qe[12*128];
__device__ float g_pg[24*128];
__device__ float g_pe[24*128];
__device__ float g_cKg[24];
__device__ float g_cKe[24];
__device__ float g_MTg[12*2*128*128];
__device__ float g_cg[12*128];
__device__ float g_MTe[2*128*128];
__device__ float g_ce[128];
__device__ float g_coef[24*17*5];
__device__ float g_coef2[206*5];
__device__ int   g_mm_cc[206];
__device__ float g_T[206*5*128];
__device__ float g_xbar[8192*12*256];
__device__ float g_r[8192*12*128];

__device__ __forceinline__ int grp_n(int i){ return i<5?7:(i<10?9:(i==10?17:6)); }
__device__ __forceinline__ int grp_s(int i){ return 2*(i<5? 7*i : (i<10? 35+9*(i-5) : (i==10? 80 : 97))); }
__device__ __forceinline__ int grp_off(int i){ int m=i%5; return m==0?3:(m==1?4:(m==2?2:(m==3?1:0))); }
__device__ __forceinline__ int member_cc(int i,int j){ return i<10 ? 5*j+grp_off(i) : (i==10?45+j:62+j); }
__device__ __forceinline__ int orig_ch(int cc){ return cc<45?cc:cc+20; }
__device__ __forceinline__ void m_decode(int m,int&ih,int&g,int&cc){
  for(int i=0;i<12;i++){ int n=grp_n(i); if(m<2*n){ int h=m/n; g=m%n; ih=2*i+h; cc=member_cc(i,g); return;} m-=2*n; }
  ih=0;g=0;cc=0;
}

// ---------------- setup 1 ----------------
__global__ void k_setup1(const float* __restrict__ cb,const float* __restrict__ cemb,
    const float* __restrict__ cq,const float* __restrict__ gw,const float* __restrict__ gb,
    const float* __restrict__ gow,const float* __restrict__ gob,const float* __restrict__ eq,
    const float* __restrict__ ew,const float* __restrict__ eb,const float* __restrict__ eow,
    const float* __restrict__ eob){
  int idx = blockIdx.x*256+threadIdx.x;
  if(idx<8704){ int cc=idx>>7,d=idx&127,c=orig_ch(cc); g_cbe[idx]=cb[c*128+d]+cemb[c*128+d]; return;}
  idx-=8704;
  if(idx<1536){ int i=idx>>7,r=idx&127; float s=gb[i*384+r];
    const float* w=gw+(i*384+r)*128; const float* q=cq+i*128;
    for(int d=0;d<128;d++) s=fmaf(q[d],w[d],s); g_qg[i*128+r]=s; return;}
  idx-=1536;
  if(idx<1536){ int t=idx>>7,r=idx&127; float s=eb[r];
    const float* w=ew+r*128; const float* q=eq+t*128;
    for(int d=0;d<128;d++) s=fmaf(q[d],w[d],s); g_qe[t*128+r]=s; return;}
  idx-=1536;
  if(idx<393216){ int i=idx>>15, rem=idx&32767, h=rem>>14, k=(rem>>7)&127, dout=rem&127;
    float s=0.f; const float* gr=gow+i*16384+dout*128+h*64;
    for(int e=0;e<64;e++) s=fmaf(gr[e], gw[(i*384+256+h*64+e)*128+k], s);
    g_MTg[((i*2+h)*128+k)*128+dout]=s; return;}
  idx-=393216;
  if(idx<1536){ int i=idx>>7,dout=idx&127; float s=gob[i*128+dout];
    const float* gr=gow+i*16384+dout*128;
    for(int r=0;r<128;r++) s=fmaf(gr[r], gb[i*384+256+r], s); g_cg[idx]=s; return;}
  idx-=1536;
  if(idx<32768){ int h=idx>>14,k=(idx>>7)&127,dout=idx&127;
    float s=0.f; const float* er=eow+dout*128+h*64;
    for(int e=0;e<64;e++) s=fmaf(er[e], ew[(256+h*64+e)*128+k], s);
    g_MTe[(h*128+k)*128+dout]=s; return;}
  idx-=32768;
  if(idx<128){ float s=eob[idx]; const float* er=eow+idx*128;
    for(int r=0;r<128;r++) s=fmaf(er[r], eb[256+r], s); g_ce[idx]=s;}
}

// ---------------- setup 2 ----------------
__global__ void k_setup2(const float* __restrict__ gw,const float* __restrict__ gb,
    const float* __restrict__ ew,const float* __restrict__ eb){
  int idx=blockIdx.x*256+threadIdx.x;
  if(idx<3072){ int ih=idx>>7,d=idx&127,i=ih>>1,h=ih&1;
    float s=0.f; const float* q=g_qg+i*128+h*64;
    for(int e=0;e<64;e++) s=fmaf(q[e], gw[(i*384+128+h*64+e)*128+d], s);
    g_pg[idx]=s*SCALEF; return;}
  idx-=3072;
  if(idx<3072){ int th=idx>>7,d=idx&127,t=th>>1,h=th&1;
    float s=0.f; const float* q=g_qe+t*128+h*64;
    for(int e=0;e<64;e++) s=fmaf(q[e], ew[(128+h*64+e)*128+d], s);
    g_pe[idx]=s*SCALEF; return;}
  idx-=3072;
  if(idx<24){ int i=idx>>1,h=idx&1; float s=0.f; const float* q=g_qg+i*128+h*64;
    for(int e=0;e<64;e++) s=fmaf(q[e], gb[i*384+128+h*64+e], s); g_cKg[idx]=s*SCALEF; return;}
  idx-=24;
  if(idx<24){ int t=idx>>1,h=idx&1; float s=0.f; const float* q=g_qe+t*128+h*64;
    for(int e=0;e<64;e++) s=fmaf(q[e], eb[128+h*64+e], s); g_cKe[idx]=s*SCALEF;}
}

// ---------------- setup 3 ----------------
__global__ void k_setup3(const float* __restrict__ conv_w){
  int idx=blockIdx.x*256+threadIdx.x;
  if(idx>=2040) return;
  int ih=idx/85, rem=idx%85, g=rem/5, p=rem%5, i=ih>>1;
  if(g>=grp_n(i)) return;
  int cc=member_cc(i,g);
  const float* pv=g_pg+ih*128;
  float s=0.f;
  if(p<4){ const float* w=conv_w+(orig_ch(cc)*4+p)*128;
    for(int d=0;d<128;d++) s=fmaf(pv[d],w[d],s);
  } else { const float* w=g_cbe+cc*128;
    for(int d=0;d<128;d++) s=fmaf(pv[d],w[d],s);
    s+=g_cKg[ih];
  }
  g_coef[(ih*17+g)*5+p]=s;
}

// ---------------- lists ----------------
__global__ void k_lists(){
  int m=threadIdx.x;
  if(m>=206) return;
  int ih,g,cc; m_decode(m,ih,g,cc);
  g_mm_cc[m]=cc;
  for(int p=0;p<5;p++) g_coef2[m*5+p]=g_coef[(ih*17+g)*5+p];
}

// ---------------- setup 4: fused member tensors ----------------
__global__ void k_setup4(const float* __restrict__ conv_w){
  int idx=blockIdx.x*256+threadIdx.x;
  if(idx>=131840) return;
  int m=idx/640, p=(idx/128)%5, dout=idx&127;
  int ih,g,cc; m_decode(m,ih,g,cc);
  const float* M=g_MTg+ih*16384;
  float s=0.f;
  if(p<4){ const float* w=conv_w+(orig_ch(cc)*4+p)*128;
    for(int k=0;k<128;k++) s=fmaf(w[k], M[k*128+dout], s);
  } else { const float* w=g_cbe+cc*128;
    for(int k=0;k<128;k++) s=fmaf(w[k], M[k*128+dout], s);
  }
  g_T[idx]=s;
}

// ---------------- K-main ----------------
__global__ void __launch_bounds__(256,3) k_main(const float* __restrict__ x){
  extern __shared__ float sm[];
  float* sp  = sm;             // 8704
  float* sa  = sm + 8704;      // 6592
  float* scf = sm + 15296;     // 1030
  int*   scc = (int*)(sm + 16326); // 206
  int tid=threadIdx.x;
  int hp = blockIdx.x>>2, wb = blockIdx.x&3;
  for(int f=tid; f<8704; f+=256){
    int cc=f>>7, r=f&127, pi=r>>6, j=r&63, t=j>>1, pj=j&1;
    sp[(cc*4+pi*2+pj)*32+t] = x[orig_ch(cc)*32768 + (2*hp+pi)*256 + wb*64 + j];
  }
  for(int f=tid; f<1030; f+=256) scf[f]=g_coef2[f];
  if(tid<206) scc[tid]=g_mm_cc[tid];
  __syncthreads();
  for(int f=tid; f<6592; f+=256){
    int m=f>>5, t=f&31;
    const float* cf=scf+m*5;
    const float* pb=sp+scc[m]*128;
    sa[f]=fmaf(cf[0],pb[t],fmaf(cf[1],pb[32+t],fmaf(cf[2],pb[64+t],fmaf(cf[3],pb[96+t],cf[4]))));
  }
  __syncthreads();
  for(int f=tid; f<768; f+=256){
    int j=f>>5, t=f&31, i=j>>1, h=j&1;
    int n=grp_n(i), st=grp_s(i)+h*n;
    float mx=-1e30f;
    for(int g=0;g<n;g++) mx=fmaxf(mx, sa[(st+g)*32+t]);
    float sum=0.f;
    for(int g=0;g<n;g++){ float e=__expf(sa[(st+g)*32+t]-mx); sa[(st+g)*32+t]=e; sum+=e; }
    float inv=1.f/sum;
    for(int g=0;g<n;g++) sa[(st+g)*32+t]*=inv;
  }
  __syncthreads();
  int d=tid&127, th=tid>>7;
  int l0=blockIdx.x*32 + th*16;
  for(int i=0;i<12;i++){
    u64 acc[8];
    u64 bias2=dup2(g_cg[i*128+d]);
    #pragma unroll
    for(int t=0;t<8;t++) acc[t]=bias2;
    int st=grp_s(i), en=st+2*grp_n(i);
    for(int m=st;m<en;m++){
      const float* T=g_T+m*640+d;
      u64 T0=dup2(T[0]),T1=dup2(T[128]),T2=dup2(T[256]),T3=dup2(T[384]),T4=dup2(T[512]);
      const float* pb=sp+scc[m]*128+th*16;
      const float* ab=sa+m*32+th*16;
      #pragma unroll
      for(int q=0;q<4;q++){
        ulonglong2 p0=*(const ulonglong2*)(pb+q*4);
        ulonglong2 p1=*(const ulonglong2*)(pb+32+q*4);
        ulonglong2 p2=*(const ulonglong2*)(pb+64+q*4);
        ulonglong2 p3=*(const ulonglong2*)(pb+96+q*4);
        ulonglong2 av=*(const ulonglong2*)(ab+q*4);
        u64 ia=fma2(T0,p0.x,fma2(T1,p1.x,fma2(T2,p2.x,fma2(T3,p3.x,T4))));
        u64 ib=fma2(T0,p0.y,fma2(T1,p1.y,fma2(T2,p2.y,fma2(T3,p3.y,T4))));
        acc[q*2]  =fma2(av.x,ia,acc[q*2]);
        acc[q*2+1]=fma2(av.y,ib,acc[q*2+1]);
      }
    }
    #pragma unroll
    for(int t=0;t<8;t++){
      float2 v=upk(acc[t]);
      g_r[((l0+t*2  )*12+i)*128+d]=v.x;
      g_r[((l0+t*2+1)*12+i)*128+d]=v.y;
    }
  }
}

// ---------------- ensemble scores + obar ----------------
__global__ void k_ens1(){
  __shared__ float sout[1536];
  __shared__ float ssc[288];
  __shared__ u64 ssc2[288];
  int tid=threadIdx.x, lane=tid&31, wid=tid>>5;
  int l=blockIdx.x;
  for(int f=tid; f<1536; f+=256) sout[f]=g_r[l*1536+f];
  __syncthreads();
  for(int dot=wid; dot<288; dot+=8){
    int th=dot/12, s=dot%12;
    const u64* p2=(const u64*)(g_pe+th*128);
    const u64* o2=(const u64*)(sout+s*128);
    u64 vp=fma2(p2[lane],o2[lane],fma2(p2[lane+32],o2[lane+32],0ull));
    float2 vv=upk(vp);
    float v=vv.x+vv.y;
    for(int off=16;off;off>>=1) v+=__shfl_xor_sync(0xffffffffu,v,off);
    if(lane==0) ssc[dot]=v+g_cKe[th];
  }
  __syncthreads();
  if(tid<24){
    float* s=ssc+tid*12;
    float mx=-1e30f; for(int j=0;j<12;j++) mx=fmaxf(mx,s[j]);
    float sum=0.f; for(int j=0;j<12;j++){ float e=__expf(s[j]-mx); s[j]=e; sum+=e; }
    float inv=1.f/sum; for(int j=0;j<12;j++) s[j]*=inv;
  }
  __syncthreads();
  for(int f=tid; f<288; f+=256) ssc2[f]=dup2(ssc[f]);
  __syncthreads();
  const u64* so2=(const u64*)sout;
  for(int o=tid;o<1536;o+=256){
    int dp=o&63, th=o>>6;
    u64 acc=0ull;
    const u64* w=ssc2+th*12;
    #pragma unroll
    for(int s=0;s<12;s++) acc=fma2(w[s], so2[s*64+dp], acc);
    ((u64*)g_xbar)[l*1536 + th*64 + dp]=acc;
  }
}

// ---------------- GEMM (f32x2): C[row][128] = A[row][256] @ MTe + ce ----------------
__global__ void __launch_bounds__(512,1) k_gemm(){
  extern __shared__ float sm[];
  float* Bs = sm;          // 256*128
  float* As = sm + 32768;  // 128*128
  int tid=threadIdx.x;
  int tc=tid&15, tr=tid>>4;    // tr: 0..31 (4 rows), tc: 0..15 (8 cols)
  int rowBase = blockIdx.x*128;
  for(int f=tid; f<8192; f+=512)
    *(float4*)(Bs + f*4) = *(const float4*)(g_MTe + f*4);
  u64 acc[4][4];
  #pragma unroll
  for(int j=0;j<4;j++){ acc[j][0]=0ull;acc[j][1]=0ull;acc[j][2]=0ull;acc[j][3]=0ull; }
  for(int half=0; half<2; half++){
    for(int f=tid; f<4096; f+=512){
      int row=f>>5, kq=f&31;
      *(float4*)(As + row*128 + kq*4) =
        *(const float4*)(g_xbar + (rowBase+row)*256 + half*128 + kq*4);
    }
    __syncthreads();
    #pragma unroll 2
    for(int k=0;k<128;k+=4){
      float4 a4[4];
      #pragma unroll
      for(int j=0;j<4;j++) a4[j]=*(float4*)(As+(tr*4+j)*128+k);
      #pragma unroll
      for(int kk=0;kk<4;kk++){
        const float* brow=Bs+(half*128+k+kk)*128+tc*8;
        ulonglong2 b01=*(const ulonglong2*)brow;
        ulonglong2 b23=*(const ulonglong2*)(brow+4);
        #pragma unroll
        for(int j=0;j<4;j++){
          float av=((const float*)&a4[j])[kk];
          u64 ad=dup2(av);
          acc[j][0]=fma2(ad,b01.x,acc[j][0]);
          acc[j][1]=fma2(ad,b01.y,acc[j][1]);
          acc[j][2]=fma2(ad,b23.x,acc[j][2]);
          acc[j][3]=fma2(ad,b23.y,acc[j][3]);
        }
      }
    }
    __syncthreads();
  }
  ulonglong2 c01=*(const ulonglong2*)(g_ce+tc*8);
  ulonglong2 c23=*(const ulonglong2*)(g_ce+tc*8+4);
  #pragma unroll
  for(int j=0;j<4;j++){
    u64 o0=add2(acc[j][0],c01.x), o1=add2(acc[j][1],c01.y);
    u64 o2=add2(acc[j][2],c23.x), o3=add2(acc[j][3],c23.y);
    u64* dst=(u64*)(g_r + (rowBase+tr*4+j)*128 + tc*8);
    ulonglong2 w0; w0.x=o0; w0.y=o1;
    ulonglong2 w1; w1.x=o2; w1.y=o3;
    *(ulonglong2*)dst = w0;
    *(ulonglong2*)(dst+2) = w1;
  }
}

// ---------------- LayerNorm ----------------
__global__ void k_ln(const float* __restrict__ gamma, const float* __restrict__ beta,
                     float* __restrict__ out){
  __shared__ float sr[1536];
  __shared__ float red[64];
  int tid=threadIdx.x, l=blockIdx.x;
  float s=0.f;
  for(int f=tid; f<1536; f+=256){ float v=g_r[l*1536+f]; sr[f]=v; s+=v; }
  for(int off=16;off;off>>=1) s+=__shfl_xor_sync(0xffffffffu,s,off);
  if((tid&31)==0) red[tid>>5]=s;
  __syncthreads();
  if(tid<8){ s=red[tid]; for(int off=4;off;off>>=1) s+=__shfl_xor_sync(0xffu,s,off); if(tid==0) red[32]=s; }
  __syncthreads();
  float mu=red[32]*(1.f/1536.f);
  float vs=0.f;
  for(int f=tid; f<1536; f+=256){ float d=sr[f]-mu; vs=fmaf(d,d,vs); }
  for(int off=16;off;off>>=1) vs+=__shfl_xor_sync(0xffffffffu,vs,off);
  if((tid&31)==0) red[tid>>5]=vs;
  __syncthreads();
  if(tid<8){ vs=red[tid]; for(int off=4;off;off>>=1) vs+=__shfl_xor_sync(0xffu,vs,off); if(tid==0) red[33]=vs; }
  __syncthreads();
  float rs=rsqrtf(red[33]*(1.f/1536.f)+1e-5f);
  for(int f=tid; f<1536; f+=256)
    out[l*1536+f]=(sr[f]-mu)*rs*gamma[f]+beta[f];
}

extern "C" void kernel_launch(void* const* d_in, const int* in_sizes, int n_in,
                              void* d_out, int out_size){
  const float* x     =(const float*)d_in[0];
  const float* conv_w=(const float*)d_in[1];
  const float* conv_b=(const float*)d_in[2];
  const float* cemb  =(const float*)d_in[3];
  const float* cq    =(const float*)d_in[4];
  const float* gw    =(const float*)d_in[5];
  const float* gb    =(const float*)d_in[6];
  const float* gow   =(const float*)d_in[7];
  const float* gob   =(const float*)d_in[8];
  const float* eq    =(const float*)d_in[9];
  const float* ew    =(const float*)d_in[10];
  const float* eb    =(const float*)d_in[11];
  const float* eow   =(const float*)d_in[12];
  const float* eob   =(const float*)d_in[13];
  const float* gamma =(const float*)d_in[14];
  const float* beta  =(const float*)d_in[15];
  float* out=(float*)d_out;

  cudaFuncSetAttribute(k_main, cudaFuncAttributeMaxDynamicSharedMemorySize, 66128);
  cudaFuncSetAttribute(k_gemm, cudaFuncAttributeMaxDynamicSharedMemorySize, 196608);

  k_setup1<<<1717,256>>>(conv_b,cemb,cq,gw,gb,gow,gob,eq,ew,eb,eow,eob);
  k_setup2<<<25,256>>>(gw,gb,ew,eb);
  k_setup3<<<8,256>>>(conv_w);
  k_lists<<<1,256>>>();
  k_setup4<<<515,256>>>(conv_w);
  k_main<<<256,256,66128>>>(x);
  k_ens1<<<8192,256>>>();
  k_gemm<<<768,512,196608>>>();
  k_ln<<<8192,256>>>(gamma,beta,out);
}

// round 6
// speedup vs baseline: 1.2887x; 1.2887x over previous
#include <cuda_runtime.h>

#define NCC 68
#define SCALEF 0.125f

// ---------------- device scratch ----------------
__device__ float g_cbe[NCC*128];
__device__ float g_qg[12*128];
__device__ float g_qe[12*128];
__device__ float g_pg[24*128];
__device__ float g_pe[24*128];
__device__ float g_cKg[24];
__device__ float g_cKe[24];
__device__ float g_MTg[12*2*128*128];
__device__ float g_cg[12*128];
__device__ float g_MTe[2*128*128];
__device__ float g_ce[128];
__device__ float g_coef[24*17*5];
__device__ float g_coef2[206*5];
__device__ int   g_mm_cc[206];
__device__ float g_T[206*5*128];
__device__ float g_xbar[8192*12*256];
__device__ float g_r[8192*12*128];

__device__ __forceinline__ int grp_n(int i){ return i<5?7:(i<10?9:(i==10?17:6)); }
__device__ __forceinline__ int grp_s(int i){ return 2*(i<5? 7*i : (i<10? 35+9*(i-5) : (i==10? 80 : 97))); }
__device__ __forceinline__ int grp_off(int i){ int m=i%5; return m==0?3:(m==1?4:(m==2?2:(m==3?1:0))); }
__device__ __forceinline__ int member_cc(int i,int j){ return i<10 ? 5*j+grp_off(i) : (i==10?45+j:62+j); }
__device__ __forceinline__ int orig_ch(int cc){ return cc<45?cc:cc+20; }
__device__ __forceinline__ void m_decode(int m,int&ih,int&g,int&cc){
  for(int i=0;i<12;i++){ int n=grp_n(i); if(m<2*n){ int h=m/n; g=m%n; ih=2*i+h; cc=member_cc(i,g); return;} m-=2*n; }
  ih=0;g=0;cc=0;
}

// ---------------- setup 1 (coalescing-fixed MTg/MTe branches) ----------------
__global__ void k_setup1(const float* __restrict__ cb,const float* __restrict__ cemb,
    const float* __restrict__ cq,const float* __restrict__ gw,const float* __restrict__ gb,
    const float* __restrict__ gow,const float* __restrict__ gob,const float* __restrict__ eq,
    const float* __restrict__ ew,const float* __restrict__ eb,const float* __restrict__ eow,
    const float* __restrict__ eob){
  int idx = blockIdx.x*256+threadIdx.x;
  if(idx<8704){ int cc=idx>>7,d=idx&127,c=orig_ch(cc); g_cbe[idx]=cb[c*128+d]+cemb[c*128+d]; return;}
  idx-=8704;
  if(idx<1536){ int i=idx>>7,r=idx&127; float s=gb[i*384+r];
    const float* w=gw+(i*384+r)*128; const float* q=cq+i*128;
    for(int d=0;d<128;d++) s=fmaf(q[d],w[d],s); g_qg[i*128+r]=s; return;}
  idx-=1536;
  if(idx<1536){ int t=idx>>7,r=idx&127; float s=eb[r];
    const float* w=ew+r*128; const float* q=eq+t*128;
    for(int d=0;d<128;d++) s=fmaf(q[d],w[d],s); g_qe[t*128+r]=s; return;}
  idx-=1536;
  if(idx<393216){ int i=idx>>15, rem=idx&32767, h=rem>>14, dout=(rem>>7)&127, k=rem&127;
    float s=0.f; const float* gr=gow+i*16384+dout*128+h*64;   // warp-uniform -> broadcast
    for(int e=0;e<64;e++) s=fmaf(gr[e], gw[(i*384+256+h*64+e)*128+k], s);  // k fast -> coalesced
    g_MTg[((i*2+h)*128+k)*128+dout]=s; return;}
  idx-=393216;
  if(idx<1536){ int i=idx>>7,dout=idx&127; float s=gob[i*128+dout];
    const float* gr=gow+i*16384+dout*128;
    for(int r=0;r<128;r++) s=fmaf(gr[r], gb[i*384+256+r], s); g_cg[idx]=s; return;}
  idx-=1536;
  if(idx<32768){ int h=idx>>14, dout=(idx>>7)&127, k=idx&127;
    float s=0.f; const float* er=eow+dout*128+h*64;           // warp-uniform
    for(int e=0;e<64;e++) s=fmaf(er[e], ew[(256+h*64+e)*128+k], s);        // coalesced
    g_MTe[(h*128+k)*128+dout]=s; return;}
  idx-=32768;
  if(idx<128){ float s=eob[idx]; const float* er=eow+idx*128;
    for(int r=0;r<128;r++) s=fmaf(er[r], eb[256+r], s); g_ce[idx]=s;}
}

// ---------------- setup 2 ----------------
__global__ void k_setup2(const float* __restrict__ gw,const float* __restrict__ gb,
    const float* __restrict__ ew,const float* __restrict__ eb){
  int idx=blockIdx.x*256+threadIdx.x;
  if(idx<3072){ int ih=idx>>7,d=idx&127,i=ih>>1,h=ih&1;
    float s=0.f; const float* q=g_qg+i*128+h*64;
    for(int e=0;e<64;e++) s=fmaf(q[e], gw[(i*384+128+h*64+e)*128+d], s);
    g_pg[idx]=s*SCALEF; return;}
  idx-=3072;
  if(idx<3072){ int th=idx>>7,d=idx&127,t=th>>1,h=th&1;
    float s=0.f; const float* q=g_qe+t*128+h*64;
    for(int e=0;e<64;e++) s=fmaf(q[e], ew[(128+h*64+e)*128+d], s);
    g_pe[idx]=s*SCALEF; return;}
  idx-=3072;
  if(idx<24){ int i=idx>>1,h=idx&1; float s=0.f; const float* q=g_qg+i*128+h*64;
    for(int e=0;e<64;e++) s=fmaf(q[e], gb[i*384+128+h*64+e], s); g_cKg[idx]=s*SCALEF; return;}
  idx-=24;
  if(idx<24){ int t=idx>>1,h=idx&1; float s=0.f; const float* q=g_qe+t*128+h*64;
    for(int e=0;e<64;e++) s=fmaf(q[e], eb[128+h*64+e], s); g_cKe[idx]=s*SCALEF;}
}

// ---------------- setup 3 ----------------
__global__ void k_setup3(const float* __restrict__ conv_w){
  int idx=blockIdx.x*256+threadIdx.x;
  if(idx>=2040) return;
  int ih=idx/85, rem=idx%85, g=rem/5, p=rem%5, i=ih>>1;
  if(g>=grp_n(i)) return;
  int cc=member_cc(i,g);
  const float* pv=g_pg+ih*128;
  float s=0.f;
  if(p<4){ const float* w=conv_w+(orig_ch(cc)*4+p)*128;
    for(int d=0;d<128;d++) s=fmaf(pv[d],w[d],s);
  } else { const float* w=g_cbe+cc*128;
    for(int d=0;d<128;d++) s=fmaf(pv[d],w[d],s);
    s+=g_cKg[ih];
  }
  g_coef[(ih*17+g)*5+p]=s;
}

// ---------------- lists ----------------
__global__ void k_lists(){
  int m=threadIdx.x;
  if(m>=206) return;
  int ih,g,cc; m_decode(m,ih,g,cc);
  g_mm_cc[m]=cc;
  for(int p=0;p<5;p++) g_coef2[m*5+p]=g_coef[(ih*17+g)*5+p];
}

// ---------------- setup 4: fused member tensors ----------------
__global__ void k_setup4(const float* __restrict__ conv_w){
  int idx=blockIdx.x*256+threadIdx.x;
  if(idx>=131840) return;
  int m=idx/640, p=(idx/128)%5, dout=idx&127;
  int ih,g,cc; m_decode(m,ih,g,cc);
  const float* M=g_MTg+ih*16384;
  float s=0.f;
  if(p<4){ const float* w=conv_w+(orig_ch(cc)*4+p)*128;
    for(int k=0;k<128;k++) s=fmaf(w[k], M[k*128+dout], s);
  } else { const float* w=g_cbe+cc*128;
    for(int k=0;k<128;k++) s=fmaf(w[k], M[k*128+dout], s);
  }
  g_T[idx]=s;
}

// ---------------- K-main (r3 scalar version) ----------------
__global__ void __launch_bounds__(256,3) k_main(const float* __restrict__ x){
  extern __shared__ float sm[];
  float* sp  = sm;             // 8704
  float* sa  = sm + 8704;      // 6592
  float* scf = sm + 15296;     // 1030
  int*   scc = (int*)(sm + 16326); // 206
  int tid=threadIdx.x;
  int hp = blockIdx.x>>2, wb = blockIdx.x&3;
  for(int f=tid; f<8704; f+=256){
    int cc=f>>7, r=f&127, pi=r>>6, j=r&63, t=j>>1, pj=j&1;
    sp[(cc*4+pi*2+pj)*32+t] = x[orig_ch(cc)*32768 + (2*hp+pi)*256 + wb*64 + j];
  }
  for(int f=tid; f<1030; f+=256) scf[f]=g_coef2[f];
  if(tid<206) scc[tid]=g_mm_cc[tid];
  __syncthreads();
  for(int f=tid; f<6592; f+=256){
    int m=f>>5, t=f&31;
    const float* cf=scf+m*5;
    const float* pb=sp+scc[m]*128;
    sa[f]=fmaf(cf[0],pb[t],fmaf(cf[1],pb[32+t],fmaf(cf[2],pb[64+t],fmaf(cf[3],pb[96+t],cf[4]))));
  }
  __syncthreads();
  for(int f=tid; f<768; f+=256){
    int j=f>>5, t=f&31, i=j>>1, h=j&1;
    int n=grp_n(i), st=grp_s(i)+h*n;
    float mx=-1e30f;
    for(int g=0;g<n;g++) mx=fmaxf(mx, sa[(st+g)*32+t]);
    float sum=0.f;
    for(int g=0;g<n;g++){ float e=__expf(sa[(st+g)*32+t]-mx); sa[(st+g)*32+t]=e; sum+=e; }
    float inv=1.f/sum;
    for(int g=0;g<n;g++) sa[(st+g)*32+t]*=inv;
  }
  __syncthreads();
  int d=tid&127, th=tid>>7;
  int l0=blockIdx.x*32 + th*16;
  for(int i=0;i<12;i++){
    float acc[16];
    float bias=g_cg[i*128+d];
    #pragma unroll
    for(int t=0;t<16;t++) acc[t]=bias;
    int st=grp_s(i), en=st+2*grp_n(i);
    for(int m=st;m<en;m++){
      const float* T=g_T+m*640+d;
      float T0=T[0],T1=T[128],T2=T[256],T3=T[384],T4=T[512];
      const float* pb=sp+scc[m]*128+th*16;
      const float* ab=sa+m*32+th*16;
      #pragma unroll
      for(int q=0;q<4;q++){
        float4 p0=*(const float4*)(pb+q*4);
        float4 p1=*(const float4*)(pb+32+q*4);
        float4 p2=*(const float4*)(pb+64+q*4);
        float4 p3=*(const float4*)(pb+96+q*4);
        float4 av=*(const float4*)(ab+q*4);
        float i0=fmaf(T0,p0.x,fmaf(T1,p1.x,fmaf(T2,p2.x,fmaf(T3,p3.x,T4))));
        float i1=fmaf(T0,p0.y,fmaf(T1,p1.y,fmaf(T2,p2.y,fmaf(T3,p3.y,T4))));
        float i2=fmaf(T0,p0.z,fmaf(T1,p1.z,fmaf(T2,p2.z,fmaf(T3,p3.z,T4))));
        float i3=fmaf(T0,p0.w,fmaf(T1,p1.w,fmaf(T2,p2.w,fmaf(T3,p3.w,T4))));
        acc[q*4+0]=fmaf(av.x,i0,acc[q*4+0]);
        acc[q*4+1]=fmaf(av.y,i1,acc[q*4+1]);
        acc[q*4+2]=fmaf(av.z,i2,acc[q*4+2]);
        acc[q*4+3]=fmaf(av.w,i3,acc[q*4+3]);
      }
    }
    #pragma unroll
    for(int t=0;t<16;t++)
      g_r[((l0+t)*12+i)*128+d]=acc[t];
  }
}

// ---------------- ensemble scores + obar (r3 version) ----------------
__global__ void k_ens1(){
  __shared__ float sout[1536];
  __shared__ float ssc[288];
  int tid=threadIdx.x, lane=tid&31, wid=tid>>5;
  int l=blockIdx.x;
  for(int f=tid; f<1536; f+=256) sout[f]=g_r[l*1536+f];
  __syncthreads();
  for(int dot=wid; dot<288; dot+=8){
    int th=dot/12, s=dot%12;
    const float* p=g_pe+th*128;
    const float* o=sout+s*128;
    float v=0.f;
    #pragma unroll
    for(int q=0;q<4;q++){ int dd=lane+32*q; v=fmaf(p[dd],o[dd],v); }
    for(int off=16;off;off>>=1) v+=__shfl_xor_sync(0xffffffffu,v,off);
    if(lane==0) ssc[dot]=v+g_cKe[th];
  }
  __syncthreads();
  if(tid<24){
    float* s=ssc+tid*12;
    float mx=-1e30f; for(int j=0;j<12;j++) mx=fmaxf(mx,s[j]);
    float sum=0.f; for(int j=0;j<12;j++){ float e=__expf(s[j]-mx); s[j]=e; sum+=e; }
    float inv=1.f/sum; for(int j=0;j<12;j++) s[j]*=inv;
  }
  __syncthreads();
  for(int o=tid;o<3072;o+=256){
    int d=o&127, th=o>>7;
    const float* w=ssc+th*12;
    float acc=0.f;
    #pragma unroll
    for(int s=0;s<12;s++) acc=fmaf(w[s], sout[s*128+d], acc);
    g_xbar[l*3072+th*128+d]=acc;
  }
}

// ---------------- fused GEMM + LayerNorm: 96 rows (8 tokens) per CTA ----------------
__global__ void __launch_bounds__(512,1) k_gemm_ln(const float* __restrict__ gamma,
    const float* __restrict__ beta, float* __restrict__ out){
  extern __shared__ float sm[];
  float* Bs = sm;            // 256*128 = 32768
  float* As = sm + 32768;    // 96*128  = 12288
  float* sg = sm + 45056;    // 1536
  float* sb = sm + 46592;    // 1536
  float* red= sm + 48128;    // 16
  int tid=threadIdx.x, tc=tid&31, rg=tid>>5;   // rg = warp = row-group (6 rows), tc = col-group (4 cols)
  int rowBase = blockIdx.x*96;
  for(int f=tid; f<8192; f+=512)
    *(float4*)(Bs+f*4)=*(const float4*)(g_MTe+f*4);
  for(int f=tid; f<384; f+=512){
    *(float4*)(sg+f*4)=*(const float4*)(gamma+f*4);
    *(float4*)(sb+f*4)=*(const float4*)(beta+f*4);
  }
  float acc[6][4];
  #pragma unroll
  for(int j=0;j<6;j++){ acc[j][0]=0.f;acc[j][1]=0.f;acc[j][2]=0.f;acc[j][3]=0.f; }
  for(int half=0; half<2; half++){
    for(int f=tid; f<3072; f+=512){
      int row=f>>5, kq=f&31;
      *(float4*)(As + row*128 + kq*4) =
        *(const float4*)(g_xbar + (rowBase+row)*256 + half*128 + kq*4);
    }
    __syncthreads();
    #pragma unroll 2
    for(int k=0;k<128;k+=4){
      float4 b4[4];
      #pragma unroll
      for(int kk=0;kk<4;kk++) b4[kk]=*(float4*)(Bs+(half*128+k+kk)*128+tc*4);
      #pragma unroll
      for(int j=0;j<6;j++){
        float4 a=*(float4*)(As+(rg*6+j)*128+k);
        float aa[4]={a.x,a.y,a.z,a.w};
        #pragma unroll
        for(int kk=0;kk<4;kk++){
          acc[j][0]=fmaf(aa[kk],b4[kk].x,acc[j][0]);
          acc[j][1]=fmaf(aa[kk],b4[kk].y,acc[j][1]);
          acc[j][2]=fmaf(aa[kk],b4[kk].z,acc[j][2]);
          acc[j][3]=fmaf(aa[kk],b4[kk].w,acc[j][3]);
        }
      }
    }
    __syncthreads();
  }
  // bias + first-pass sum (two warps 2t,2t+1 own token t)
  float4 bi=*(const float4*)(g_ce+tc*4);
  float lsum=0.f;
  #pragma unroll
  for(int j=0;j<6;j++){
    acc[j][0]+=bi.x; acc[j][1]+=bi.y; acc[j][2]+=bi.z; acc[j][3]+=bi.w;
    lsum += acc[j][0]+acc[j][1]+acc[j][2]+acc[j][3];
  }
  for(int off=16;off;off>>=1) lsum+=__shfl_xor_sync(0xffffffffu,lsum,off);
  if(tc==0) red[rg]=lsum;
  __syncthreads();
  float mu=(red[rg&~1]+red[rg|1])*(1.f/1536.f);
  __syncthreads();
  float lsq=0.f;
  #pragma unroll
  for(int j=0;j<6;j++){
    #pragma unroll
    for(int c=0;c<4;c++){ float dd=acc[j][c]-mu; lsq=fmaf(dd,dd,lsq); }
  }
  for(int off=16;off;off>>=1) lsq+=__shfl_xor_sync(0xffffffffu,lsq,off);
  if(tc==0) red[rg]=lsq;
  __syncthreads();
  float rs=rsqrtf((red[rg&~1]+red[rg|1])*(1.f/1536.f)+1e-5f);
  #pragma unroll
  for(int j=0;j<6;j++){
    int row=rg*6+j;              // local row; token t'= row%12
    int tp=row%12;
    float4 gm=*(const float4*)(sg+tp*128+tc*4);
    float4 bt=*(const float4*)(sb+tp*128+tc*4);
    float4 o;
    o.x=(acc[j][0]-mu)*rs*gm.x+bt.x;
    o.y=(acc[j][1]-mu)*rs*gm.y+bt.y;
    o.z=(acc[j][2]-mu)*rs*gm.z+bt.z;
    o.w=(acc[j][3]-mu)*rs*gm.w+bt.w;
    *(float4*)(out + (rowBase+row)*128 + tc*4) = o;
  }
}

extern "C" void kernel_launch(void* const* d_in, const int* in_sizes, int n_in,
                              void* d_out, int out_size){
  const float* x     =(const float*)d_in[0];
  const float* conv_w=(const float*)d_in[1];
  const float* conv_b=(const float*)d_in[2];
  const float* cemb  =(const float*)d_in[3];
  const float* cq    =(const float*)d_in[4];
  const float* gw    =(const float*)d_in[5];
  const float* gb    =(const float*)d_in[6];
  const float* gow   =(const float*)d_in[7];
  const float* gob   =(const float*)d_in[8];
  const float* eq    =(const float*)d_in[9];
  const float* ew    =(const float*)d_in[10];
  const float* eb    =(const float*)d_in[11];
  const float* eow   =(const float*)d_in[12];
  const float* eob   =(const float*)d_in[13];
  const float* gamma =(const float*)d_in[14];
  const float* beta  =(const float*)d_in[15];
  float* out=(float*)d_out;

  cudaFuncSetAttribute(k_main,    cudaFuncAttributeMaxDynamicSharedMemorySize, 66128);
  cudaFuncSetAttribute(k_gemm_ln, cudaFuncAttributeMaxDynamicSharedMemorySize, 192640);

  k_setup1<<<1717,256>>>(conv_b,cemb,cq,gw,gb,gow,gob,eq,ew,eb,eow,eob);
  k_setup2<<<25,256>>>(gw,gb,ew,eb);
  k_setup3<<<8,256>>>(conv_w);
  k_lists<<<1,256>>>();
  k_setup4<<<515,256>>>(conv_w);
  k_main<<<256,256,66128>>>(x);
  k_ens1<<<8192,256>>>();
  k_gemm_ln<<<1024,512,192640>>>(gamma,beta,out);
}